// round 8
// baseline (speedup 1.0000x reference)
#include <cuda_runtime.h>
#include <cuda_bf16.h>
#include <cstdint>
#include <math.h>

#define T_DIM 4096
#define C_DIM 1024
#define HF_DIM 4096
#define NH 16
#define HD 64

typedef __nv_bfloat16 bf16;

// ---------------- scratch ----------------
__device__ float g_qkv[T_DIM * 3 * C_DIM];
__device__ float g_x2 [T_DIM * C_DIM];

__device__ bf16 g_xn_h [T_DIM * C_DIM];
__device__ bf16 g_xn_l [T_DIM * C_DIM];
__device__ bf16 g_y_h  [T_DIM * C_DIM];
__device__ bf16 g_y_l  [T_DIM * C_DIM];
__device__ bf16 g_xn2_h[T_DIM * C_DIM];
__device__ bf16 g_xn2_l[T_DIM * C_DIM];
__device__ bf16 g_hg_h [T_DIM * HF_DIM];
__device__ bf16 g_hg_l [T_DIM * HF_DIM];

__device__ bf16 g_wqkv_h[3 * C_DIM * C_DIM];
__device__ bf16 g_wqkv_l[3 * C_DIM * C_DIM];
__device__ bf16 g_wpro_h[C_DIM * C_DIM];
__device__ bf16 g_wpro_l[C_DIM * C_DIM];
__device__ bf16 g_w13_h[2 * HF_DIM * C_DIM];   // interleaved: row 2n=w1[n], 2n+1=w3[n]
__device__ bf16 g_w13_l[2 * HF_DIM * C_DIM];
__device__ bf16 g_w2_h[C_DIM * HF_DIM];
__device__ bf16 g_w2_l[C_DIM * HF_DIM];

// ================= helpers =================
static __device__ __forceinline__ void mma_bf16(float* c, const uint32_t* a,
                                                const uint32_t* b) {
    asm volatile(
        "mma.sync.aligned.m16n8k16.row.col.f32.bf16.bf16.f32 "
        "{%0,%1,%2,%3}, {%4,%5,%6,%7}, {%8,%9}, {%0,%1,%2,%3};"
        : "+f"(c[0]), "+f"(c[1]), "+f"(c[2]), "+f"(c[3])
        : "r"(a[0]), "r"(a[1]), "r"(a[2]), "r"(a[3]), "r"(b[0]), "r"(b[1]));
}
static __device__ __forceinline__ uint32_t pack_bf2(float x, float y) {
    __nv_bfloat162 h;
    h.x = __float2bfloat16(x);
    h.y = __float2bfloat16(y);
    return *(uint32_t*)&h;
}
static __device__ __forceinline__ float bf_lo_res(float v, uint32_t packed, int hi) {
    __nv_bfloat162* p = (__nv_bfloat162*)&packed;
    return v - __bfloat162float(hi ? p->y : p->x);
}
static __device__ __forceinline__ uint32_t smem_u32(const void* p) {
    uint32_t a;
    asm("{ .reg .u64 t; cvta.to.shared.u64 t, %1; cvt.u32.u64 %0, t; }" : "=r"(a) : "l"(p));
    return a;
}

// ---------------- split fp32 -> (hi, lo) bf16 ----------------
__global__ __launch_bounds__(256) void split_kernel(const float* __restrict__ in,
                                                    bf16* __restrict__ oh,
                                                    bf16* __restrict__ ol, int n4) {
    int i = blockIdx.x * blockDim.x + threadIdx.x;
    if (i < n4) {
        float4 v = ((const float4*)in)[i];
        uint32_t h01 = pack_bf2(v.x, v.y), h23 = pack_bf2(v.z, v.w);
        uint32_t l01 = pack_bf2(bf_lo_res(v.x, h01, 0), bf_lo_res(v.y, h01, 1));
        uint32_t l23 = pack_bf2(bf_lo_res(v.z, h23, 0), bf_lo_res(v.w, h23, 1));
        ((uint2*)oh)[i] = make_uint2(h01, h23);
        ((uint2*)ol)[i] = make_uint2(l01, l23);
    }
}

// ---------------- split + interleave w1/w3 into [2*Hf, C] ----------------
__global__ __launch_bounds__(256) void split_w13(const float* __restrict__ w1,
                                                 const float* __restrict__ w3,
                                                 bf16* __restrict__ oh,
                                                 bf16* __restrict__ ol) {
    int i = blockIdx.x * blockDim.x + threadIdx.x;
    int row = i / (C_DIM / 4);
    int c4 = i % (C_DIM / 4);
#pragma unroll
    for (int s = 0; s < 2; s++) {
        const float* src = s ? w3 : w1;
        float4 v = ((const float4*)(src + (size_t)row * C_DIM))[c4];
        uint32_t h01 = pack_bf2(v.x, v.y), h23 = pack_bf2(v.z, v.w);
        uint32_t l01 = pack_bf2(bf_lo_res(v.x, h01, 0), bf_lo_res(v.y, h01, 1));
        uint32_t l23 = pack_bf2(bf_lo_res(v.z, h23, 0), bf_lo_res(v.w, h23, 1));
        size_t off = (size_t)(2 * row + s) * (C_DIM / 4) + c4;
        ((uint2*)oh)[off] = make_uint2(h01, h23);
        ((uint2*)ol)[off] = make_uint2(l01, l23);
    }
}

// ================= gemm_bf: 128x128 tile (R7-proven) — used for N=1024 GEMMs ======
#define GPITCH 40
#define GARR (128 * GPITCH)
#define GSTAGE (4 * GARR)
#define GEMM_SMEM (2 * GSTAGE * 2)

template <int MODE>
__global__ __launch_bounds__(256, 2) void gemm_bf(const bf16* __restrict__ Ah,
                                                  const bf16* __restrict__ Al,
                                                  const bf16* __restrict__ Bh,
                                                  const bf16* __restrict__ Bl,
                                                  const float* __restrict__ R,
                                                  float* __restrict__ C,
                                                  bf16* __restrict__ Oh,
                                                  bf16* __restrict__ Ol,
                                                  int M, int N, int K) {
    extern __shared__ bf16 sh[];
    const int t = threadIdx.x;
    const int w = t >> 5;
    const int lane = t & 31;
    const int g = lane >> 2;
    const int tig = lane & 3;
    const int wm = w >> 2;
    const int wn = w & 3;

    const int m0 = blockIdx.y << 7;
    const int n0 = blockIdx.x << 7;
    const int nk = K >> 5;
    const uint32_t sbase = smem_u32(sh);

    const bf16* srcs[4] = {Ah + (size_t)m0 * K, Al + (size_t)m0 * K,
                           Bh + (size_t)n0 * K, Bl + (size_t)n0 * K};

    const int lrow = t >> 2;
    const int lch = (t & 3) << 3;

    auto load_stage = [&](int i) {
        const int st = i & 1;
        const int k0 = i << 5;
#pragma unroll
        for (int arr = 0; arr < 4; arr++) {
#pragma unroll
            for (int it = 0; it < 2; it++) {
                int row = lrow + (it << 6);
                const bf16* gp = srcs[arr] + (size_t)row * K + k0 + lch;
                uint32_t sa = sbase + (uint32_t)(st * GSTAGE + arr * GARR + row * GPITCH + lch) * 2u;
                asm volatile("cp.async.cg.shared.global [%0], [%1], 16;" :: "r"(sa), "l"(gp));
            }
        }
        asm volatile("cp.async.commit_group;" ::: "memory");
    };

    float acc[4][4][4] = {};
    load_stage(0);

    for (int i = 0; i < nk; i++) {
        if (i + 1 < nk) {
            load_stage(i + 1);
            asm volatile("cp.async.wait_group 1;" ::: "memory");
        } else {
            asm volatile("cp.async.wait_group 0;" ::: "memory");
        }
        __syncthreads();

        const bf16* Ahs = sh + (i & 1) * GSTAGE;
        const bf16* Als = Ahs + GARR;
        const bf16* Bhs = Ahs + 2 * GARR;
        const bf16* Bls = Ahs + 3 * GARR;

#pragma unroll
        for (int kk = 0; kk < 32; kk += 16) {
            uint32_t ahi[4][4], alo[4][4], bhi[4][2], blo[4][2];
#pragma unroll
            for (int mi = 0; mi < 4; mi++) {
                int r = wm * 64 + mi * 16 + g;
                int c = kk + tig * 2;
                ahi[mi][0] = *(const uint32_t*)(Ahs + r * GPITCH + c);
                ahi[mi][1] = *(const uint32_t*)(Ahs + (r + 8) * GPITCH + c);
                ahi[mi][2] = *(const uint32_t*)(Ahs + r * GPITCH + c + 8);
                ahi[mi][3] = *(const uint32_t*)(Ahs + (r + 8) * GPITCH + c + 8);
                alo[mi][0] = *(const uint32_t*)(Als + r * GPITCH + c);
                alo[mi][1] = *(const uint32_t*)(Als + (r + 8) * GPITCH + c);
                alo[mi][2] = *(const uint32_t*)(Als + r * GPITCH + c + 8);
                alo[mi][3] = *(const uint32_t*)(Als + (r + 8) * GPITCH + c + 8);
            }
#pragma unroll
            for (int ni = 0; ni < 4; ni++) {
                int n = wn * 32 + ni * 8 + g;
                int c = kk + tig * 2;
                bhi[ni][0] = *(const uint32_t*)(Bhs + n * GPITCH + c);
                bhi[ni][1] = *(const uint32_t*)(Bhs + n * GPITCH + c + 8);
                blo[ni][0] = *(const uint32_t*)(Bls + n * GPITCH + c);
                blo[ni][1] = *(const uint32_t*)(Bls + n * GPITCH + c + 8);
            }
#pragma unroll
            for (int mi = 0; mi < 4; mi++)
#pragma unroll
                for (int ni = 0; ni < 4; ni++) {
                    mma_bf16(acc[mi][ni], ahi[mi], bhi[ni]);
                    mma_bf16(acc[mi][ni], ahi[mi], blo[ni]);
                    mma_bf16(acc[mi][ni], alo[mi], bhi[ni]);
                }
        }
        __syncthreads();
    }

#pragma unroll
    for (int mi = 0; mi < 4; mi++) {
        int r = m0 + wm * 64 + mi * 16 + g;
#pragma unroll
        for (int ni = 0; ni < 4; ni++) {
            int col = n0 + wn * 32 + ni * 8 + tig * 2;
            float2 v0 = make_float2(acc[mi][ni][0], acc[mi][ni][1]);
            float2 v1 = make_float2(acc[mi][ni][2], acc[mi][ni][3]);
            size_t o0 = (size_t)r * N + col;
            size_t o1 = (size_t)(r + 8) * N + col;
            if (R) {
                float2 r0 = *(const float2*)(R + o0);
                float2 r1 = *(const float2*)(R + o1);
                v0.x += r0.x; v0.y += r0.y;
                v1.x += r1.x; v1.y += r1.y;
            }
            *(float2*)(C + o0) = v0;
            *(float2*)(C + o1) = v1;
        }
    }
}

// ================= gemm_wide: 128x256 tile, warp tile 64x64 — qkv & w13 =========
// MODE 0: fp32 out (+R). MODE 1: gated FFN epilogue -> split bf16.
#define WPITCH 40
#define WA_ELE (128 * WPITCH)          // 5120
#define WB_ELE (256 * WPITCH)          // 10240
#define WSTAGE (2 * WA_ELE + 2 * WB_ELE)  // 30720 bf16
#define GEMMW_SMEM (2 * WSTAGE * 2)       // 122880 bytes

template <int MODE>
__global__ __launch_bounds__(256, 1) void gemm_wide(const bf16* __restrict__ Ah,
                                                    const bf16* __restrict__ Al,
                                                    const bf16* __restrict__ Bh,
                                                    const bf16* __restrict__ Bl,
                                                    float* __restrict__ C,
                                                    bf16* __restrict__ Oh,
                                                    bf16* __restrict__ Ol,
                                                    int M, int N, int K) {
    extern __shared__ bf16 sh[];
    const int t = threadIdx.x;
    const int w = t >> 5;
    const int lane = t & 31;
    const int g = lane >> 2;
    const int tig = lane & 3;
    const int wm = w >> 2;      // 0..1
    const int wn = w & 3;       // 0..3 (64 cols each)

    const int m0 = blockIdx.y << 7;
    const int n0 = blockIdx.x << 8;
    const int nk = K >> 5;
    const uint32_t sbase = smem_u32(sh);

    const bf16* srcA[2] = {Ah + (size_t)m0 * K, Al + (size_t)m0 * K};
    const bf16* srcB[2] = {Bh + (size_t)n0 * K, Bl + (size_t)n0 * K};

    const int lrow = t >> 2;
    const int lch = (t & 3) << 3;

    auto load_stage = [&](int i) {
        const int st = i & 1;
        const int k0 = i << 5;
#pragma unroll
        for (int arr = 0; arr < 2; arr++) {
#pragma unroll
            for (int it = 0; it < 2; it++) {
                int row = lrow + (it << 6);
                const bf16* gp = srcA[arr] + (size_t)row * K + k0 + lch;
                uint32_t sa = sbase + (uint32_t)(st * WSTAGE + arr * WA_ELE + row * WPITCH + lch) * 2u;
                asm volatile("cp.async.cg.shared.global [%0], [%1], 16;" :: "r"(sa), "l"(gp));
            }
        }
#pragma unroll
        for (int arr = 0; arr < 2; arr++) {
#pragma unroll
            for (int it = 0; it < 4; it++) {
                int row = lrow + (it << 6);
                const bf16* gp = srcB[arr] + (size_t)row * K + k0 + lch;
                uint32_t sa = sbase + (uint32_t)(st * WSTAGE + 2 * WA_ELE + arr * WB_ELE + row * WPITCH + lch) * 2u;
                asm volatile("cp.async.cg.shared.global [%0], [%1], 16;" :: "r"(sa), "l"(gp));
            }
        }
        asm volatile("cp.async.commit_group;" ::: "memory");
    };

    float acc[4][8][4] = {};
    load_stage(0);

    for (int i = 0; i < nk; i++) {
        if (i + 1 < nk) {
            load_stage(i + 1);
            asm volatile("cp.async.wait_group 1;" ::: "memory");
        } else {
            asm volatile("cp.async.wait_group 0;" ::: "memory");
        }
        __syncthreads();

        const bf16* Ahs = sh + (i & 1) * WSTAGE;
        const bf16* Als = Ahs + WA_ELE;
        const bf16* Bhs = Ahs + 2 * WA_ELE;
        const bf16* Bls = Bhs + WB_ELE;

#pragma unroll
        for (int kk = 0; kk < 32; kk += 16) {
            const int c = kk + tig * 2;
            uint32_t ahi[4][4], alo[4][4];
#pragma unroll
            for (int mi = 0; mi < 4; mi++) {
                int r = wm * 64 + mi * 16 + g;
                ahi[mi][0] = *(const uint32_t*)(Ahs + r * WPITCH + c);
                ahi[mi][1] = *(const uint32_t*)(Ahs + (r + 8) * WPITCH + c);
                ahi[mi][2] = *(const uint32_t*)(Ahs + r * WPITCH + c + 8);
                ahi[mi][3] = *(const uint32_t*)(Ahs + (r + 8) * WPITCH + c + 8);
                alo[mi][0] = *(const uint32_t*)(Als + r * WPITCH + c);
                alo[mi][1] = *(const uint32_t*)(Als + (r + 8) * WPITCH + c);
                alo[mi][2] = *(const uint32_t*)(Als + r * WPITCH + c + 8);
                alo[mi][3] = *(const uint32_t*)(Als + (r + 8) * WPITCH + c + 8);
            }
#pragma unroll
            for (int ni = 0; ni < 8; ni++) {
                int n = wn * 64 + ni * 8 + g;
                uint32_t bhi[2], blo[2];
                bhi[0] = *(const uint32_t*)(Bhs + n * WPITCH + c);
                bhi[1] = *(const uint32_t*)(Bhs + n * WPITCH + c + 8);
                blo[0] = *(const uint32_t*)(Bls + n * WPITCH + c);
                blo[1] = *(const uint32_t*)(Bls + n * WPITCH + c + 8);
#pragma unroll
                for (int mi = 0; mi < 4; mi++) {
                    mma_bf16(acc[mi][ni], ahi[mi], bhi);
                    mma_bf16(acc[mi][ni], ahi[mi], blo);
                    mma_bf16(acc[mi][ni], alo[mi], bhi);
                }
            }
        }
        __syncthreads();
    }

    if (MODE == 0) {
#pragma unroll
        for (int mi = 0; mi < 4; mi++) {
            int r = m0 + wm * 64 + mi * 16 + g;
#pragma unroll
            for (int ni = 0; ni < 8; ni++) {
                int col = n0 + wn * 64 + ni * 8 + tig * 2;
                *(float2*)(C + (size_t)r * N + col) = make_float2(acc[mi][ni][0], acc[mi][ni][1]);
                *(float2*)(C + (size_t)(r + 8) * N + col) = make_float2(acc[mi][ni][2], acc[mi][ni][3]);
            }
        }
    } else {
        const int NU = N >> 1;
#pragma unroll
        for (int mi = 0; mi < 4; mi++) {
            int r = m0 + wm * 64 + mi * 16 + g;
#pragma unroll
            for (int ni = 0; ni < 8; ni++) {
                int col = n0 + wn * 64 + ni * 8 + tig * 2;
                int u = col >> 1;
                float h1v = acc[mi][ni][0], h3v = acc[mi][ni][1];
                float g0 = h1v / (1.f + __expf(-h1v)) * h3v;
                float h1b = acc[mi][ni][2], h3b = acc[mi][ni][3];
                float g1 = h1b / (1.f + __expf(-h1b)) * h3b;
                bf16 g0h = __float2bfloat16(g0);
                bf16 g1h = __float2bfloat16(g1);
                Oh[(size_t)r * NU + u] = g0h;
                Ol[(size_t)r * NU + u] = __float2bfloat16(g0 - __bfloat162float(g0h));
                Oh[(size_t)(r + 8) * NU + u] = g1h;
                Ol[(size_t)(r + 8) * NU + u] = __float2bfloat16(g1 - __bfloat162float(g1h));
            }
        }
    }
}

// ================= tensor-core flash attention (unchanged) =================
#define AP 72
#define SQH 0
#define SQL (128 * AP)
#define SKH (256 * AP)
#define SKL (320 * AP)
#define SVH (384 * AP)
#define SVL (448 * AP)
#define ATTN_SMEM (512 * AP * 2)

__global__ __launch_bounds__(256) void attn_mma(const float* __restrict__ qkv,
                                                bf16* __restrict__ yh,
                                                bf16* __restrict__ yl) {
    extern __shared__ bf16 asm_[];
    const int h = blockIdx.y;
    const int q0 = blockIdx.x << 7;
    const int t = threadIdx.x;
    const int w = t >> 5;
    const int lane = t & 31;
    const int g = lane >> 2;
    const int tig = lane & 3;

#pragma unroll
    for (int it = 0; it < 8; it++) {
        int idx = t + (it << 8);
        int row = idx >> 4, c4 = idx & 15;
        float4 v = *(const float4*)(qkv + (size_t)(q0 + row) * (3 * C_DIM) + h * HD + (c4 << 2));
        v.x *= 0.125f; v.y *= 0.125f; v.z *= 0.125f; v.w *= 0.125f;
        uint32_t h01 = pack_bf2(v.x, v.y), h23 = pack_bf2(v.z, v.w);
        uint32_t l01 = pack_bf2(bf_lo_res(v.x, h01, 0), bf_lo_res(v.y, h01, 1));
        uint32_t l23 = pack_bf2(bf_lo_res(v.z, h23, 0), bf_lo_res(v.w, h23, 1));
        int off = row * AP + (c4 << 2);
        *(uint2*)(asm_ + SQH + off) = make_uint2(h01, h23);
        *(uint2*)(asm_ + SQL + off) = make_uint2(l01, l23);
    }
    __syncthreads();

    uint32_t qh[4][4], ql[4][4];
    {
        int r = w * 16 + g;
#pragma unroll
        for (int ks = 0; ks < 4; ks++) {
            int c = ks * 16 + tig * 2;
            qh[ks][0] = *(const uint32_t*)(asm_ + SQH + r * AP + c);
            qh[ks][1] = *(const uint32_t*)(asm_ + SQH + (r + 8) * AP + c);
            qh[ks][2] = *(const uint32_t*)(asm_ + SQH + r * AP + c + 8);
            qh[ks][3] = *(const uint32_t*)(asm_ + SQH + (r + 8) * AP + c + 8);
            ql[ks][0] = *(const uint32_t*)(asm_ + SQL + r * AP + c);
            ql[ks][1] = *(const uint32_t*)(asm_ + SQL + (r + 8) * AP + c);
            ql[ks][2] = *(const uint32_t*)(asm_ + SQL + r * AP + c + 8);
            ql[ks][3] = *(const uint32_t*)(asm_ + SQL + (r + 8) * AP + c + 8);
        }
    }

    float o[8][4] = {};
    float m0 = -1e30f, m1 = -1e30f, l0 = 0.f, l1 = 0.f;
    const int ntile = (q0 >> 6) + 2;
    const int r0 = q0 + w * 16 + g;
    const int r1 = r0 + 8;

    for (int jt = 0; jt < ntile; jt++) {
        const int j0 = jt << 6;
#pragma unroll
        for (int it = 0; it < 4; it++) {
            int idx = t + (it << 8);
            int row = idx >> 4, c4 = idx & 15;
            float4 v = *(const float4*)(qkv + (size_t)(j0 + row) * (3 * C_DIM) + C_DIM + h * HD + (c4 << 2));
            uint32_t h01 = pack_bf2(v.x, v.y), h23 = pack_bf2(v.z, v.w);
            uint32_t l01 = pack_bf2(bf_lo_res(v.x, h01, 0), bf_lo_res(v.y, h01, 1));
            uint32_t l23 = pack_bf2(bf_lo_res(v.z, h23, 0), bf_lo_res(v.w, h23, 1));
            int off = row * AP + (c4 << 2);
            *(uint2*)(asm_ + SKH + off) = make_uint2(h01, h23);
            *(uint2*)(asm_ + SKL + off) = make_uint2(l01, l23);
        }
#pragma unroll
        for (int it = 0; it < 4; it++) {
            int idx = t + (it << 8);
            int row = idx >> 4, c4 = idx & 15;
            float4 v = *(const float4*)(qkv + (size_t)(j0 + row) * (3 * C_DIM) + 2 * C_DIM + h * HD + (c4 << 2));
            float vv[4] = {v.x, v.y, v.z, v.w};
#pragma unroll
            for (int i = 0; i < 4; i++) {
                int d = (c4 << 2) + i;
                bf16 hb = __float2bfloat16(vv[i]);
                asm_[SVH + d * AP + row] = hb;
                asm_[SVL + d * AP + row] = __float2bfloat16(vv[i] - __bfloat162float(hb));
            }
        }
        __syncthreads();

        float s[8][4];
#pragma unroll
        for (int nb = 0; nb < 8; nb++) {
            s[nb][0] = 0.f; s[nb][1] = 0.f; s[nb][2] = 0.f; s[nb][3] = 0.f;
            int n = nb * 8 + g;
#pragma unroll
            for (int ks = 0; ks < 4; ks++) {
                int c = ks * 16 + tig * 2;
                uint32_t bh[2], bl[2];
                bh[0] = *(const uint32_t*)(asm_ + SKH + n * AP + c);
                bh[1] = *(const uint32_t*)(asm_ + SKH + n * AP + c + 8);
                bl[0] = *(const uint32_t*)(asm_ + SKL + n * AP + c);
                bl[1] = *(const uint32_t*)(asm_ + SKL + n * AP + c + 8);
                mma_bf16(s[nb], qh[ks], bh);
                mma_bf16(s[nb], qh[ks], bl);
                mma_bf16(s[nb], ql[ks], bh);
            }
        }

        if (jt >= ntile - 2) {
#pragma unroll
            for (int nb = 0; nb < 8; nb++) {
                int c0 = j0 + nb * 8 + tig * 2;
                if (c0 > r0)     s[nb][0] = -1e30f;
                if (c0 + 1 > r0) s[nb][1] = -1e30f;
                if (c0 > r1)     s[nb][2] = -1e30f;
                if (c0 + 1 > r1) s[nb][3] = -1e30f;
            }
        }

        float tm0 = -1e30f, tm1 = -1e30f;
#pragma unroll
        for (int nb = 0; nb < 8; nb++) {
            tm0 = fmaxf(tm0, fmaxf(s[nb][0], s[nb][1]));
            tm1 = fmaxf(tm1, fmaxf(s[nb][2], s[nb][3]));
        }
        tm0 = fmaxf(tm0, __shfl_xor_sync(~0u, tm0, 1));
        tm0 = fmaxf(tm0, __shfl_xor_sync(~0u, tm0, 2));
        tm1 = fmaxf(tm1, __shfl_xor_sync(~0u, tm1, 1));
        tm1 = fmaxf(tm1, __shfl_xor_sync(~0u, tm1, 2));
        float nm0 = fmaxf(m0, tm0), nm1 = fmaxf(m1, tm1);
        float a0 = __expf(m0 - nm0), a1 = __expf(m1 - nm1);
        m0 = nm0; m1 = nm1;
        float rs0 = 0.f, rs1 = 0.f;
#pragma unroll
        for (int nb = 0; nb < 8; nb++) {
            s[nb][0] = __expf(s[nb][0] - nm0);
            s[nb][1] = __expf(s[nb][1] - nm0);
            s[nb][2] = __expf(s[nb][2] - nm1);
            s[nb][3] = __expf(s[nb][3] - nm1);
            rs0 += s[nb][0] + s[nb][1];
            rs1 += s[nb][2] + s[nb][3];
        }
        rs0 += __shfl_xor_sync(~0u, rs0, 1);
        rs0 += __shfl_xor_sync(~0u, rs0, 2);
        rs1 += __shfl_xor_sync(~0u, rs1, 1);
        rs1 += __shfl_xor_sync(~0u, rs1, 2);
        l0 = l0 * a0 + rs0;
        l1 = l1 * a1 + rs1;
#pragma unroll
        for (int nd = 0; nd < 8; nd++) {
            o[nd][0] *= a0; o[nd][1] *= a0; o[nd][2] *= a1; o[nd][3] *= a1;
        }

#pragma unroll
        for (int kb = 0; kb < 4; kb++) {
            uint32_t ph[4], pl[4];
            {
                float* sa = s[2 * kb];
                float* sb = s[2 * kb + 1];
                ph[0] = pack_bf2(sa[0], sa[1]);
                pl[0] = pack_bf2(bf_lo_res(sa[0], ph[0], 0), bf_lo_res(sa[1], ph[0], 1));
                ph[1] = pack_bf2(sa[2], sa[3]);
                pl[1] = pack_bf2(bf_lo_res(sa[2], ph[1], 0), bf_lo_res(sa[3], ph[1], 1));
                ph[2] = pack_bf2(sb[0], sb[1]);
                pl[2] = pack_bf2(bf_lo_res(sb[0], ph[2], 0), bf_lo_res(sb[1], ph[2], 1));
                ph[3] = pack_bf2(sb[2], sb[3]);
                pl[3] = pack_bf2(bf_lo_res(sb[2], ph[3], 0), bf_lo_res(sb[3], ph[3], 1));
            }
            int c = kb * 16 + tig * 2;
#pragma unroll
            for (int nd = 0; nd < 8; nd++) {
                int n = nd * 8 + g;
                uint32_t vh[2], vl[2];
                vh[0] = *(const uint32_t*)(asm_ + SVH + n * AP + c);
                vh[1] = *(const uint32_t*)(asm_ + SVH + n * AP + c + 8);
                vl[0] = *(const uint32_t*)(asm_ + SVL + n * AP + c);
                vl[1] = *(const uint32_t*)(asm_ + SVL + n * AP + c + 8);
                mma_bf16(o[nd], ph, vh);
                mma_bf16(o[nd], pl, vh);
                mma_bf16(o[nd], ph, vl);
            }
        }
        __syncthreads();
    }

    float il0 = 1.0f / l0, il1 = 1.0f / l1;
#pragma unroll
    for (int nd = 0; nd < 8; nd++) {
        int col = h * HD + nd * 8 + tig * 2;
        float v00 = o[nd][0] * il0, v01 = o[nd][1] * il0;
        float v10 = o[nd][2] * il1, v11 = o[nd][3] * il1;
        uint32_t h0 = pack_bf2(v00, v01);
        uint32_t l0p = pack_bf2(bf_lo_res(v00, h0, 0), bf_lo_res(v01, h0, 1));
        uint32_t h1v = pack_bf2(v10, v11);
        uint32_t l1p = pack_bf2(bf_lo_res(v10, h1v, 0), bf_lo_res(v11, h1v, 1));
        *(uint32_t*)(yh + (size_t)r0 * C_DIM + col) = h0;
        *(uint32_t*)(yl + (size_t)r0 * C_DIM + col) = l0p;
        *(uint32_t*)(yh + (size_t)r1 * C_DIM + col) = h1v;
        *(uint32_t*)(yl + (size_t)r1 * C_DIM + col) = l1p;
    }
}

// ---------------- rmsnorm -> split bf16 ----------------
__global__ __launch_bounds__(256) void rmsnorm_split(const float* __restrict__ x,
                                                     const float* __restrict__ w,
                                                     bf16* __restrict__ oh,
                                                     bf16* __restrict__ ol) {
    int row = blockIdx.x;
    int t = threadIdx.x;
    const float4* xr = (const float4*)(x + (size_t)row * C_DIM);
    float4 v = xr[t];
    float ss = v.x * v.x + v.y * v.y + v.z * v.z + v.w * v.w;
    __shared__ float red[8];
#pragma unroll
    for (int off = 16; off; off >>= 1) ss += __shfl_xor_sync(~0u, ss, off);
    if ((t & 31) == 0) red[t >> 5] = ss;
    __syncthreads();
    if (t < 32) {
        float s2 = (t < 8) ? red[t] : 0.f;
#pragma unroll
        for (int off = 4; off; off >>= 1) s2 += __shfl_xor_sync(~0u, s2, off);
        if (t == 0) red[0] = s2;
    }
    __syncthreads();
    float rn = rsqrtf(red[0] * (1.0f / C_DIM) + 1e-6f);
    float4 wv = ((const float4*)w)[t];
    float4 ov = make_float4(v.x * rn * wv.x, v.y * rn * wv.y, v.z * rn * wv.z, v.w * rn * wv.w);
    uint32_t h01 = pack_bf2(ov.x, ov.y), h23 = pack_bf2(ov.z, ov.w);
    uint32_t l01 = pack_bf2(bf_lo_res(ov.x, h01, 0), bf_lo_res(ov.y, h01, 1));
    uint32_t l23 = pack_bf2(bf_lo_res(ov.z, h23, 0), bf_lo_res(ov.w, h23, 1));
    ((uint2*)(oh + (size_t)row * C_DIM))[t] = make_uint2(h01, h23);
    ((uint2*)(ol + (size_t)row * C_DIM))[t] = make_uint2(l01, l23);
}

// ---------------- orchestration ----------------
extern "C" void kernel_launch(void* const* d_in, const int* in_sizes, int n_in,
                              void* d_out, int out_size) {
    const float* x      = (const float*)d_in[0];
    const float* anw    = (const float*)d_in[1];
    const float* fnw    = (const float*)d_in[2];
    const float* c_attn = (const float*)d_in[3];
    const float* c_proj = (const float*)d_in[4];
    const float* w1     = (const float*)d_in[5];
    const float* w2     = (const float*)d_in[6];
    const float* w3     = (const float*)d_in[7];
    float* out = (float*)d_out;

    float *qkv, *x2;
    bf16 *xnh, *xnl, *yh, *yl, *xn2h, *xn2l, *hgh, *hgl;
    bf16 *wqh, *wql, *wph, *wpl, *w13h, *w13l, *w2h, *w2l;
    cudaGetSymbolAddress((void**)&qkv,  g_qkv);
    cudaGetSymbolAddress((void**)&x2,   g_x2);
    cudaGetSymbolAddress((void**)&xnh,  g_xn_h);
    cudaGetSymbolAddress((void**)&xnl,  g_xn_l);
    cudaGetSymbolAddress((void**)&yh,   g_y_h);
    cudaGetSymbolAddress((void**)&yl,   g_y_l);
    cudaGetSymbolAddress((void**)&xn2h, g_xn2_h);
    cudaGetSymbolAddress((void**)&xn2l, g_xn2_l);
    cudaGetSymbolAddress((void**)&hgh,  g_hg_h);
    cudaGetSymbolAddress((void**)&hgl,  g_hg_l);
    cudaGetSymbolAddress((void**)&wqh,  g_wqkv_h);
    cudaGetSymbolAddress((void**)&wql,  g_wqkv_l);
    cudaGetSymbolAddress((void**)&wph,  g_wpro_h);
    cudaGetSymbolAddress((void**)&wpl,  g_wpro_l);
    cudaGetSymbolAddress((void**)&w13h, g_w13_h);
    cudaGetSymbolAddress((void**)&w13l, g_w13_l);
    cudaGetSymbolAddress((void**)&w2h,  g_w2_h);
    cudaGetSymbolAddress((void**)&w2l,  g_w2_l);

    cudaFuncSetAttribute(gemm_bf<0>,
                         cudaFuncAttributeMaxDynamicSharedMemorySize, GEMM_SMEM);
    cudaFuncSetAttribute(gemm_wide<0>,
                         cudaFuncAttributeMaxDynamicSharedMemorySize, GEMMW_SMEM);
    cudaFuncSetAttribute(gemm_wide<1>,
                         cudaFuncAttributeMaxDynamicSharedMemorySize, GEMMW_SMEM);
    cudaFuncSetAttribute(attn_mma,
                         cudaFuncAttributeMaxDynamicSharedMemorySize, ATTN_SMEM);

    // 0) split weights
    split_kernel<<<3 * C_DIM * C_DIM / 1024, 256>>>(c_attn, wqh, wql, 3 * C_DIM * C_DIM / 4);
    split_kernel<<<C_DIM * C_DIM / 1024, 256>>>(c_proj, wph, wpl, C_DIM * C_DIM / 4);
    split_w13<<<HF_DIM * C_DIM / 1024, 256>>>(w1, w3, w13h, w13l);
    split_kernel<<<C_DIM * HF_DIM / 1024, 256>>>(w2, w2h, w2l, C_DIM * HF_DIM / 4);

    // 1) xn = rmsnorm(x) -> split
    rmsnorm_split<<<T_DIM, 256>>>(x, anw, xnh, xnl);

    // 2) qkv = xn @ c_attn^T  (wide tile)
    gemm_wide<0><<<dim3(3 * C_DIM / 256, T_DIM / 128), 256, GEMMW_SMEM>>>(
        xnh, xnl, wqh, wql, qkv, nullptr, nullptr, T_DIM, 3 * C_DIM, C_DIM);

    // 3) y = attention(qkv) -> split
    attn_mma<<<dim3(T_DIM / 128, NH), 256, ATTN_SMEM>>>(qkv, yh, yl);

    // 4) x2 = y @ c_proj^T + x
    gemm_bf<0><<<dim3(C_DIM / 128, T_DIM / 128), 256, GEMM_SMEM>>>(
        yh, yl, wph, wpl, x, x2, nullptr, nullptr, T_DIM, C_DIM, C_DIM);

    // 5) xn2 = rmsnorm(x2) -> split
    rmsnorm_split<<<T_DIM, 256>>>(x2, fnw, xn2h, xn2l);

    // 6+7) hg = silu(xn2@w1^T) * (xn2@w3^T) -> split (wide tile, fused epilogue)
    gemm_wide<1><<<dim3(2 * HF_DIM / 256, T_DIM / 128), 256, GEMMW_SMEM>>>(
        xn2h, xn2l, w13h, w13l, nullptr, hgh, hgl, T_DIM, 2 * HF_DIM, C_DIM);

    // 8) out = hg @ w2^T + x2
    gemm_bf<0><<<dim3(C_DIM / 128, T_DIM / 128), 256, GEMM_SMEM>>>(
        hgh, hgl, w2h, w2l, x2, out, nullptr, nullptr, T_DIM, C_DIM, HF_DIM);
}

// round 9
// speedup vs baseline: 1.0646x; 1.0646x over previous
#include <cuda_runtime.h>
#include <cuda_bf16.h>
#include <cstdint>
#include <math.h>

#define T_DIM 4096
#define C_DIM 1024
#define HF_DIM 4096
#define NH 16
#define HD 64

typedef __nv_bfloat16 bf16;

// ---------------- scratch ----------------
__device__ float g_qkv[T_DIM * 3 * C_DIM];
__device__ float g_x2 [T_DIM * C_DIM];

__device__ bf16 g_xn_h [T_DIM * C_DIM];
__device__ bf16 g_xn_l [T_DIM * C_DIM];
__device__ bf16 g_y_h  [T_DIM * C_DIM];
__device__ bf16 g_y_l  [T_DIM * C_DIM];
__device__ bf16 g_xn2_h[T_DIM * C_DIM];
__device__ bf16 g_xn2_l[T_DIM * C_DIM];
__device__ bf16 g_hg_h [T_DIM * HF_DIM];
__device__ bf16 g_hg_l [T_DIM * HF_DIM];

__device__ bf16 g_wqkv_h[3 * C_DIM * C_DIM];
__device__ bf16 g_wqkv_l[3 * C_DIM * C_DIM];
__device__ bf16 g_wpro_h[C_DIM * C_DIM];
__device__ bf16 g_wpro_l[C_DIM * C_DIM];
__device__ bf16 g_w13_h[2 * HF_DIM * C_DIM];   // interleaved: row 2n=w1[n], 2n+1=w3[n]
__device__ bf16 g_w13_l[2 * HF_DIM * C_DIM];
__device__ bf16 g_w2_h[C_DIM * HF_DIM];
__device__ bf16 g_w2_l[C_DIM * HF_DIM];

// ================= helpers =================
static __device__ __forceinline__ void mma_bf16(float* c, const uint32_t* a,
                                                const uint32_t* b) {
    asm volatile(
        "mma.sync.aligned.m16n8k16.row.col.f32.bf16.bf16.f32 "
        "{%0,%1,%2,%3}, {%4,%5,%6,%7}, {%8,%9}, {%0,%1,%2,%3};"
        : "+f"(c[0]), "+f"(c[1]), "+f"(c[2]), "+f"(c[3])
        : "r"(a[0]), "r"(a[1]), "r"(a[2]), "r"(a[3]), "r"(b[0]), "r"(b[1]));
}
static __device__ __forceinline__ uint32_t pack_bf2(float x, float y) {
    __nv_bfloat162 h;
    h.x = __float2bfloat16(x);
    h.y = __float2bfloat16(y);
    return *(uint32_t*)&h;
}
static __device__ __forceinline__ float bf_lo_res(float v, uint32_t packed, int hi) {
    __nv_bfloat162* p = (__nv_bfloat162*)&packed;
    return v - __bfloat162float(hi ? p->y : p->x);
}
static __device__ __forceinline__ uint32_t smem_u32(const void* p) {
    uint32_t a;
    asm("{ .reg .u64 t; cvta.to.shared.u64 t, %1; cvt.u32.u64 %0, t; }" : "=r"(a) : "l"(p));
    return a;
}
#define LDMX4(r, a) \
    asm volatile("ldmatrix.sync.aligned.m8n8.x4.shared.b16 {%0,%1,%2,%3}, [%4];" \
                 : "=r"((r)[0]), "=r"((r)[1]), "=r"((r)[2]), "=r"((r)[3]) : "r"(a))
#define LDMX2(r, a) \
    asm volatile("ldmatrix.sync.aligned.m8n8.x2.shared.b16 {%0,%1}, [%2];" \
                 : "=r"((r)[0]), "=r"((r)[1]) : "r"(a))

// ---------------- split fp32 -> (hi, lo) bf16 ----------------
__global__ __launch_bounds__(256) void split_kernel(const float* __restrict__ in,
                                                    bf16* __restrict__ oh,
                                                    bf16* __restrict__ ol, int n4) {
    int i = blockIdx.x * blockDim.x + threadIdx.x;
    if (i < n4) {
        float4 v = ((const float4*)in)[i];
        uint32_t h01 = pack_bf2(v.x, v.y), h23 = pack_bf2(v.z, v.w);
        uint32_t l01 = pack_bf2(bf_lo_res(v.x, h01, 0), bf_lo_res(v.y, h01, 1));
        uint32_t l23 = pack_bf2(bf_lo_res(v.z, h23, 0), bf_lo_res(v.w, h23, 1));
        ((uint2*)oh)[i] = make_uint2(h01, h23);
        ((uint2*)ol)[i] = make_uint2(l01, l23);
    }
}

// ---------------- split + interleave w1/w3 into [2*Hf, C] ----------------
__global__ __launch_bounds__(256) void split_w13(const float* __restrict__ w1,
                                                 const float* __restrict__ w3,
                                                 bf16* __restrict__ oh,
                                                 bf16* __restrict__ ol) {
    int i = blockIdx.x * blockDim.x + threadIdx.x;
    int row = i / (C_DIM / 4);
    int c4 = i % (C_DIM / 4);
#pragma unroll
    for (int s = 0; s < 2; s++) {
        const float* src = s ? w3 : w1;
        float4 v = ((const float4*)(src + (size_t)row * C_DIM))[c4];
        uint32_t h01 = pack_bf2(v.x, v.y), h23 = pack_bf2(v.z, v.w);
        uint32_t l01 = pack_bf2(bf_lo_res(v.x, h01, 0), bf_lo_res(v.y, h01, 1));
        uint32_t l23 = pack_bf2(bf_lo_res(v.z, h23, 0), bf_lo_res(v.w, h23, 1));
        size_t off = (size_t)(2 * row + s) * (C_DIM / 4) + c4;
        ((uint2*)oh)[off] = make_uint2(h01, h23);
        ((uint2*)ol)[off] = make_uint2(l01, l23);
    }
}

// ================= pipelined bf16 GEMM: 128x128 tile, ldmatrix fragments =========
// MODE 0: C[M,N] = A@B^T (+R), fp32 out.
// MODE 1: gated FFN epilogue: unit u = col/2, g = silu(c_even)*c_odd -> split bf16.
#define GPITCH 40
#define GARR (128 * GPITCH)
#define GSTAGE (4 * GARR)
#define GEMM_SMEM (2 * GSTAGE * 2)

template <int MODE>
__global__ __launch_bounds__(256, 2) void gemm_bf(const bf16* __restrict__ Ah,
                                                  const bf16* __restrict__ Al,
                                                  const bf16* __restrict__ Bh,
                                                  const bf16* __restrict__ Bl,
                                                  const float* __restrict__ R,
                                                  float* __restrict__ C,
                                                  bf16* __restrict__ Oh,
                                                  bf16* __restrict__ Ol,
                                                  int M, int N, int K) {
    extern __shared__ bf16 sh[];
    const int t = threadIdx.x;
    const int w = t >> 5;
    const int lane = t & 31;
    const int g = lane >> 2;
    const int tig = lane & 3;
    const int wm = w >> 2;
    const int wn = w & 3;

    const int m0 = blockIdx.y << 7;
    const int n0 = blockIdx.x << 7;
    const int nk = K >> 5;
    const uint32_t sbase = smem_u32(sh);

    const bf16* srcs[4] = {Ah + (size_t)m0 * K, Al + (size_t)m0 * K,
                           Bh + (size_t)n0 * K, Bl + (size_t)n0 * K};

    const int lrow = t >> 2;
    const int lch = (t & 3) << 3;

    auto load_stage = [&](int i) {
        const int st = i & 1;
        const int k0 = i << 5;
#pragma unroll
        for (int arr = 0; arr < 4; arr++) {
#pragma unroll
            for (int it = 0; it < 2; it++) {
                int row = lrow + (it << 6);
                const bf16* gp = srcs[arr] + (size_t)row * K + k0 + lch;
                uint32_t sa = sbase + (uint32_t)(st * GSTAGE + arr * GARR + row * GPITCH + lch) * 2u;
                asm volatile("cp.async.cg.shared.global [%0], [%1], 16;" :: "r"(sa), "l"(gp));
            }
        }
        asm volatile("cp.async.commit_group;" ::: "memory");
    };

    // ---- ldmatrix base addresses (bytes, stage 0, kk=0, hi arrays) ----
    const int aq = lane >> 3;
    const int arow = ((aq & 1) << 3) + (lane & 7);
    const int acol = (aq >> 1) << 3;
    const int bl15 = lane & 15;
    const int brow = bl15 & 7;
    const int bcol = (bl15 >> 3) << 3;

    uint32_t aAddr[4], bAddr[4];
#pragma unroll
    for (int mi = 0; mi < 4; mi++)
        aAddr[mi] = sbase + (uint32_t)((wm * 64 + mi * 16 + arow) * GPITCH + acol) * 2u;
#pragma unroll
    for (int ni = 0; ni < 4; ni++)
        bAddr[ni] = sbase + (uint32_t)(2 * GARR + (wn * 32 + ni * 8 + brow) * GPITCH + bcol) * 2u;

    float acc[4][4][4] = {};
    load_stage(0);

    for (int i = 0; i < nk; i++) {
        if (i + 1 < nk) {
            load_stage(i + 1);
            asm volatile("cp.async.wait_group 1;" ::: "memory");
        } else {
            asm volatile("cp.async.wait_group 0;" ::: "memory");
        }
        __syncthreads();

        const uint32_t stoff = (uint32_t)((i & 1) * GSTAGE) * 2u;
#pragma unroll
        for (int kk = 0; kk < 32; kk += 16) {
            const uint32_t stk = stoff + (uint32_t)kk * 2u;
            uint32_t ahi[4][4], alo[4][4], bhi[4][2], blo[4][2];
#pragma unroll
            for (int mi = 0; mi < 4; mi++) {
                uint32_t a0 = aAddr[mi] + stk;
                LDMX4(ahi[mi], a0);
                LDMX4(alo[mi], a0 + GARR * 2u);
            }
#pragma unroll
            for (int ni = 0; ni < 4; ni++) {
                uint32_t b0 = bAddr[ni] + stk;
                LDMX2(bhi[ni], b0);
                LDMX2(blo[ni], b0 + GARR * 2u);
            }
#pragma unroll
            for (int mi = 0; mi < 4; mi++)
#pragma unroll
                for (int ni = 0; ni < 4; ni++) {
                    mma_bf16(acc[mi][ni], ahi[mi], bhi[ni]);
                    mma_bf16(acc[mi][ni], ahi[mi], blo[ni]);
                    mma_bf16(acc[mi][ni], alo[mi], bhi[ni]);
                }
        }
        __syncthreads();
    }

    if (MODE == 0) {
#pragma unroll
        for (int mi = 0; mi < 4; mi++) {
            int r = m0 + wm * 64 + mi * 16 + g;
#pragma unroll
            for (int ni = 0; ni < 4; ni++) {
                int col = n0 + wn * 32 + ni * 8 + tig * 2;
                float2 v0 = make_float2(acc[mi][ni][0], acc[mi][ni][1]);
                float2 v1 = make_float2(acc[mi][ni][2], acc[mi][ni][3]);
                size_t o0 = (size_t)r * N + col;
                size_t o1 = (size_t)(r + 8) * N + col;
                if (R) {
                    float2 r0 = *(const float2*)(R + o0);
                    float2 r1 = *(const float2*)(R + o1);
                    v0.x += r0.x; v0.y += r0.y;
                    v1.x += r1.x; v1.y += r1.y;
                }
                *(float2*)(C + o0) = v0;
                *(float2*)(C + o1) = v1;
            }
        }
    } else {
        const int NU = N >> 1;
#pragma unroll
        for (int mi = 0; mi < 4; mi++) {
            int r = m0 + wm * 64 + mi * 16 + g;
#pragma unroll
            for (int ni = 0; ni < 4; ni++) {
                int col = n0 + wn * 32 + ni * 8 + tig * 2;
                int u = col >> 1;
                float h1v = acc[mi][ni][0], h3v = acc[mi][ni][1];
                float g0 = h1v / (1.f + __expf(-h1v)) * h3v;
                float h1b = acc[mi][ni][2], h3b = acc[mi][ni][3];
                float g1 = h1b / (1.f + __expf(-h1b)) * h3b;
                bf16 g0h = __float2bfloat16(g0);
                bf16 g1h = __float2bfloat16(g1);
                Oh[(size_t)r * NU + u] = g0h;
                Ol[(size_t)r * NU + u] = __float2bfloat16(g0 - __bfloat162float(g0h));
                Oh[(size_t)(r + 8) * NU + u] = g1h;
                Ol[(size_t)(r + 8) * NU + u] = __float2bfloat16(g1 - __bfloat162float(g1h));
            }
        }
    }
}

// ================= tensor-core flash attention (unchanged) =================
#define AP 72
#define SQH 0
#define SQL (128 * AP)
#define SKH (256 * AP)
#define SKL (320 * AP)
#define SVH (384 * AP)
#define SVL (448 * AP)
#define ATTN_SMEM (512 * AP * 2)

__global__ __launch_bounds__(256) void attn_mma(const float* __restrict__ qkv,
                                                bf16* __restrict__ yh,
                                                bf16* __restrict__ yl) {
    extern __shared__ bf16 asm_[];
    const int h = blockIdx.y;
    const int q0 = blockIdx.x << 7;
    const int t = threadIdx.x;
    const int w = t >> 5;
    const int lane = t & 31;
    const int g = lane >> 2;
    const int tig = lane & 3;

#pragma unroll
    for (int it = 0; it < 8; it++) {
        int idx = t + (it << 8);
        int row = idx >> 4, c4 = idx & 15;
        float4 v = *(const float4*)(qkv + (size_t)(q0 + row) * (3 * C_DIM) + h * HD + (c4 << 2));
        v.x *= 0.125f; v.y *= 0.125f; v.z *= 0.125f; v.w *= 0.125f;
        uint32_t h01 = pack_bf2(v.x, v.y), h23 = pack_bf2(v.z, v.w);
        uint32_t l01 = pack_bf2(bf_lo_res(v.x, h01, 0), bf_lo_res(v.y, h01, 1));
        uint32_t l23 = pack_bf2(bf_lo_res(v.z, h23, 0), bf_lo_res(v.w, h23, 1));
        int off = row * AP + (c4 << 2);
        *(uint2*)(asm_ + SQH + off) = make_uint2(h01, h23);
        *(uint2*)(asm_ + SQL + off) = make_uint2(l01, l23);
    }
    __syncthreads();

    uint32_t qh[4][4], ql[4][4];
    {
        int r = w * 16 + g;
#pragma unroll
        for (int ks = 0; ks < 4; ks++) {
            int c = ks * 16 + tig * 2;
            qh[ks][0] = *(const uint32_t*)(asm_ + SQH + r * AP + c);
            qh[ks][1] = *(const uint32_t*)(asm_ + SQH + (r + 8) * AP + c);
            qh[ks][2] = *(const uint32_t*)(asm_ + SQH + r * AP + c + 8);
            qh[ks][3] = *(const uint32_t*)(asm_ + SQH + (r + 8) * AP + c + 8);
            ql[ks][0] = *(const uint32_t*)(asm_ + SQL + r * AP + c);
            ql[ks][1] = *(const uint32_t*)(asm_ + SQL + (r + 8) * AP + c);
            ql[ks][2] = *(const uint32_t*)(asm_ + SQL + r * AP + c + 8);
            ql[ks][3] = *(const uint32_t*)(asm_ + SQL + (r + 8) * AP + c + 8);
        }
    }

    float o[8][4] = {};
    float m0 = -1e30f, m1 = -1e30f, l0 = 0.f, l1 = 0.f;
    const int ntile = (q0 >> 6) + 2;
    const int r0 = q0 + w * 16 + g;
    const int r1 = r0 + 8;

    for (int jt = 0; jt < ntile; jt++) {
        const int j0 = jt << 6;
#pragma unroll
        for (int it = 0; it < 4; it++) {
            int idx = t + (it << 8);
            int row = idx >> 4, c4 = idx & 15;
            float4 v = *(const float4*)(qkv + (size_t)(j0 + row) * (3 * C_DIM) + C_DIM + h * HD + (c4 << 2));
            uint32_t h01 = pack_bf2(v.x, v.y), h23 = pack_bf2(v.z, v.w);
            uint32_t l01 = pack_bf2(bf_lo_res(v.x, h01, 0), bf_lo_res(v.y, h01, 1));
            uint32_t l23 = pack_bf2(bf_lo_res(v.z, h23, 0), bf_lo_res(v.w, h23, 1));
            int off = row * AP + (c4 << 2);
            *(uint2*)(asm_ + SKH + off) = make_uint2(h01, h23);
            *(uint2*)(asm_ + SKL + off) = make_uint2(l01, l23);
        }
#pragma unroll
        for (int it = 0; it < 4; it++) {
            int idx = t + (it << 8);
            int row = idx >> 4, c4 = idx & 15;
            float4 v = *(const float4*)(qkv + (size_t)(j0 + row) * (3 * C_DIM) + 2 * C_DIM + h * HD + (c4 << 2));
            float vv[4] = {v.x, v.y, v.z, v.w};
#pragma unroll
            for (int i = 0; i < 4; i++) {
                int d = (c4 << 2) + i;
                bf16 hb = __float2bfloat16(vv[i]);
                asm_[SVH + d * AP + row] = hb;
                asm_[SVL + d * AP + row] = __float2bfloat16(vv[i] - __bfloat162float(hb));
            }
        }
        __syncthreads();

        float s[8][4];
#pragma unroll
        for (int nb = 0; nb < 8; nb++) {
            s[nb][0] = 0.f; s[nb][1] = 0.f; s[nb][2] = 0.f; s[nb][3] = 0.f;
            int n = nb * 8 + g;
#pragma unroll
            for (int ks = 0; ks < 4; ks++) {
                int c = ks * 16 + tig * 2;
                uint32_t bh[2], bl[2];
                bh[0] = *(const uint32_t*)(asm_ + SKH + n * AP + c);
                bh[1] = *(const uint32_t*)(asm_ + SKH + n * AP + c + 8);
                bl[0] = *(const uint32_t*)(asm_ + SKL + n * AP + c);
                bl[1] = *(const uint32_t*)(asm_ + SKL + n * AP + c + 8);
                mma_bf16(s[nb], qh[ks], bh);
                mma_bf16(s[nb], qh[ks], bl);
                mma_bf16(s[nb], ql[ks], bh);
            }
        }

        if (jt >= ntile - 2) {
#pragma unroll
            for (int nb = 0; nb < 8; nb++) {
                int c0 = j0 + nb * 8 + tig * 2;
                if (c0 > r0)     s[nb][0] = -1e30f;
                if (c0 + 1 > r0) s[nb][1] = -1e30f;
                if (c0 > r1)     s[nb][2] = -1e30f;
                if (c0 + 1 > r1) s[nb][3] = -1e30f;
            }
        }

        float tm0 = -1e30f, tm1 = -1e30f;
#pragma unroll
        for (int nb = 0; nb < 8; nb++) {
            tm0 = fmaxf(tm0, fmaxf(s[nb][0], s[nb][1]));
            tm1 = fmaxf(tm1, fmaxf(s[nb][2], s[nb][3]));
        }
        tm0 = fmaxf(tm0, __shfl_xor_sync(~0u, tm0, 1));
        tm0 = fmaxf(tm0, __shfl_xor_sync(~0u, tm0, 2));
        tm1 = fmaxf(tm1, __shfl_xor_sync(~0u, tm1, 1));
        tm1 = fmaxf(tm1, __shfl_xor_sync(~0u, tm1, 2));
        float nm0 = fmaxf(m0, tm0), nm1 = fmaxf(m1, tm1);
        float a0 = __expf(m0 - nm0), a1 = __expf(m1 - nm1);
        m0 = nm0; m1 = nm1;
        float rs0 = 0.f, rs1 = 0.f;
#pragma unroll
        for (int nb = 0; nb < 8; nb++) {
            s[nb][0] = __expf(s[nb][0] - nm0);
            s[nb][1] = __expf(s[nb][1] - nm0);
            s[nb][2] = __expf(s[nb][2] - nm1);
            s[nb][3] = __expf(s[nb][3] - nm1);
            rs0 += s[nb][0] + s[nb][1];
            rs1 += s[nb][2] + s[nb][3];
        }
        rs0 += __shfl_xor_sync(~0u, rs0, 1);
        rs0 += __shfl_xor_sync(~0u, rs0, 2);
        rs1 += __shfl_xor_sync(~0u, rs1, 1);
        rs1 += __shfl_xor_sync(~0u, rs1, 2);
        l0 = l0 * a0 + rs0;
        l1 = l1 * a1 + rs1;
#pragma unroll
        for (int nd = 0; nd < 8; nd++) {
            o[nd][0] *= a0; o[nd][1] *= a0; o[nd][2] *= a1; o[nd][3] *= a1;
        }

#pragma unroll
        for (int kb = 0; kb < 4; kb++) {
            uint32_t ph[4], pl[4];
            {
                float* sa = s[2 * kb];
                float* sb = s[2 * kb + 1];
                ph[0] = pack_bf2(sa[0], sa[1]);
                pl[0] = pack_bf2(bf_lo_res(sa[0], ph[0], 0), bf_lo_res(sa[1], ph[0], 1));
                ph[1] = pack_bf2(sa[2], sa[3]);
                pl[1] = pack_bf2(bf_lo_res(sa[2], ph[1], 0), bf_lo_res(sa[3], ph[1], 1));
                ph[2] = pack_bf2(sb[0], sb[1]);
                pl[2] = pack_bf2(bf_lo_res(sb[0], ph[2], 0), bf_lo_res(sb[1], ph[2], 1));
                ph[3] = pack_bf2(sb[2], sb[3]);
                pl[3] = pack_bf2(bf_lo_res(sb[2], ph[3], 0), bf_lo_res(sb[3], ph[3], 1));
            }
            int c = kb * 16 + tig * 2;
#pragma unroll
            for (int nd = 0; nd < 8; nd++) {
                int n = nd * 8 + g;
                uint32_t vh[2], vl[2];
                vh[0] = *(const uint32_t*)(asm_ + SVH + n * AP + c);
                vh[1] = *(const uint32_t*)(asm_ + SVH + n * AP + c + 8);
                vl[0] = *(const uint32_t*)(asm_ + SVL + n * AP + c);
                vl[1] = *(const uint32_t*)(asm_ + SVL + n * AP + c + 8);
                mma_bf16(o[nd], ph, vh);
                mma_bf16(o[nd], pl, vh);
                mma_bf16(o[nd], ph, vl);
            }
        }
        __syncthreads();
    }

    float il0 = 1.0f / l0, il1 = 1.0f / l1;
#pragma unroll
    for (int nd = 0; nd < 8; nd++) {
        int col = h * HD + nd * 8 + tig * 2;
        float v00 = o[nd][0] * il0, v01 = o[nd][1] * il0;
        float v10 = o[nd][2] * il1, v11 = o[nd][3] * il1;
        uint32_t h0 = pack_bf2(v00, v01);
        uint32_t l0p = pack_bf2(bf_lo_res(v00, h0, 0), bf_lo_res(v01, h0, 1));
        uint32_t h1v = pack_bf2(v10, v11);
        uint32_t l1p = pack_bf2(bf_lo_res(v10, h1v, 0), bf_lo_res(v11, h1v, 1));
        *(uint32_t*)(yh + (size_t)r0 * C_DIM + col) = h0;
        *(uint32_t*)(yl + (size_t)r0 * C_DIM + col) = l0p;
        *(uint32_t*)(yh + (size_t)r1 * C_DIM + col) = h1v;
        *(uint32_t*)(yl + (size_t)r1 * C_DIM + col) = l1p;
    }
}

// ---------------- rmsnorm -> split bf16 ----------------
__global__ __launch_bounds__(256) void rmsnorm_split(const float* __restrict__ x,
                                                     const float* __restrict__ w,
                                                     bf16* __restrict__ oh,
                                                     bf16* __restrict__ ol) {
    int row = blockIdx.x;
    int t = threadIdx.x;
    const float4* xr = (const float4*)(x + (size_t)row * C_DIM);
    float4 v = xr[t];
    float ss = v.x * v.x + v.y * v.y + v.z * v.z + v.w * v.w;
    __shared__ float red[8];
#pragma unroll
    for (int off = 16; off; off >>= 1) ss += __shfl_xor_sync(~0u, ss, off);
    if ((t & 31) == 0) red[t >> 5] = ss;
    __syncthreads();
    if (t < 32) {
        float s2 = (t < 8) ? red[t] : 0.f;
#pragma unroll
        for (int off = 4; off; off >>= 1) s2 += __shfl_xor_sync(~0u, s2, off);
        if (t == 0) red[0] = s2;
    }
    __syncthreads();
    float rn = rsqrtf(red[0] * (1.0f / C_DIM) + 1e-6f);
    float4 wv = ((const float4*)w)[t];
    float4 ov = make_float4(v.x * rn * wv.x, v.y * rn * wv.y, v.z * rn * wv.z, v.w * rn * wv.w);
    uint32_t h01 = pack_bf2(ov.x, ov.y), h23 = pack_bf2(ov.z, ov.w);
    uint32_t l01 = pack_bf2(bf_lo_res(ov.x, h01, 0), bf_lo_res(ov.y, h01, 1));
    uint32_t l23 = pack_bf2(bf_lo_res(ov.z, h23, 0), bf_lo_res(ov.w, h23, 1));
    ((uint2*)(oh + (size_t)row * C_DIM))[t] = make_uint2(h01, h23);
    ((uint2*)(ol + (size_t)row * C_DIM))[t] = make_uint2(l01, l23);
}

// ---------------- orchestration ----------------
extern "C" void kernel_launch(void* const* d_in, const int* in_sizes, int n_in,
                              void* d_out, int out_size) {
    const float* x      = (const float*)d_in[0];
    const float* anw    = (const float*)d_in[1];
    const float* fnw    = (const float*)d_in[2];
    const float* c_attn = (const float*)d_in[3];
    const float* c_proj = (const float*)d_in[4];
    const float* w1     = (const float*)d_in[5];
    const float* w2     = (const float*)d_in[6];
    const float* w3     = (const float*)d_in[7];
    float* out = (float*)d_out;

    float *qkv, *x2;
    bf16 *xnh, *xnl, *yh, *yl, *xn2h, *xn2l, *hgh, *hgl;
    bf16 *wqh, *wql, *wph, *wpl, *w13h, *w13l, *w2h, *w2l;
    cudaGetSymbolAddress((void**)&qkv,  g_qkv);
    cudaGetSymbolAddress((void**)&x2,   g_x2);
    cudaGetSymbolAddress((void**)&xnh,  g_xn_h);
    cudaGetSymbolAddress((void**)&xnl,  g_xn_l);
    cudaGetSymbolAddress((void**)&yh,   g_y_h);
    cudaGetSymbolAddress((void**)&yl,   g_y_l);
    cudaGetSymbolAddress((void**)&xn2h, g_xn2_h);
    cudaGetSymbolAddress((void**)&xn2l, g_xn2_l);
    cudaGetSymbolAddress((void**)&hgh,  g_hg_h);
    cudaGetSymbolAddress((void**)&hgl,  g_hg_l);
    cudaGetSymbolAddress((void**)&wqh,  g_wqkv_h);
    cudaGetSymbolAddress((void**)&wql,  g_wqkv_l);
    cudaGetSymbolAddress((void**)&wph,  g_wpro_h);
    cudaGetSymbolAddress((void**)&wpl,  g_wpro_l);
    cudaGetSymbolAddress((void**)&w13h, g_w13_h);
    cudaGetSymbolAddress((void**)&w13l, g_w13_l);
    cudaGetSymbolAddress((void**)&w2h,  g_w2_h);
    cudaGetSymbolAddress((void**)&w2l,  g_w2_l);

    cudaFuncSetAttribute(gemm_bf<0>,
                         cudaFuncAttributeMaxDynamicSharedMemorySize, GEMM_SMEM);
    cudaFuncSetAttribute(gemm_bf<1>,
                         cudaFuncAttributeMaxDynamicSharedMemorySize, GEMM_SMEM);
    cudaFuncSetAttribute(attn_mma,
                         cudaFuncAttributeMaxDynamicSharedMemorySize, ATTN_SMEM);

    // 0) split weights
    split_kernel<<<3 * C_DIM * C_DIM / 1024, 256>>>(c_attn, wqh, wql, 3 * C_DIM * C_DIM / 4);
    split_kernel<<<C_DIM * C_DIM / 1024, 256>>>(c_proj, wph, wpl, C_DIM * C_DIM / 4);
    split_w13<<<HF_DIM * C_DIM / 1024, 256>>>(w1, w3, w13h, w13l);
    split_kernel<<<C_DIM * HF_DIM / 1024, 256>>>(w2, w2h, w2l, C_DIM * HF_DIM / 4);

    // 1) xn = rmsnorm(x) -> split
    rmsnorm_split<<<T_DIM, 256>>>(x, anw, xnh, xnl);

    // 2) qkv = xn @ c_attn^T
    gemm_bf<0><<<dim3(3 * C_DIM / 128, T_DIM / 128), 256, GEMM_SMEM>>>(
        xnh, xnl, wqh, wql, nullptr, qkv, nullptr, nullptr, T_DIM, 3 * C_DIM, C_DIM);

    // 3) y = attention(qkv) -> split
    attn_mma<<<dim3(T_DIM / 128, NH), 256, ATTN_SMEM>>>(qkv, yh, yl);

    // 4) x2 = y @ c_proj^T + x
    gemm_bf<0><<<dim3(C_DIM / 128, T_DIM / 128), 256, GEMM_SMEM>>>(
        yh, yl, wph, wpl, x, x2, nullptr, nullptr, T_DIM, C_DIM, C_DIM);

    // 5) xn2 = rmsnorm(x2) -> split
    rmsnorm_split<<<T_DIM, 256>>>(x2, fnw, xn2h, xn2l);

    // 6+7) hg = silu(xn2@w1^T) * (xn2@w3^T) -> split (fused, interleaved weights)
    gemm_bf<1><<<dim3(2 * HF_DIM / 128, T_DIM / 128), 256, GEMM_SMEM>>>(
        xn2h, xn2l, w13h, w13l, nullptr, nullptr, hgh, hgl, T_DIM, 2 * HF_DIM, C_DIM);

    // 8) out = hg @ w2^T + x2
    gemm_bf<0><<<dim3(C_DIM / 128, T_DIM / 128), 256, GEMM_SMEM>>>(
        hgh, hgl, w2h, w2l, x2, out, nullptr, nullptr, T_DIM, C_DIM, HF_DIM);
}